// round 5
// baseline (speedup 1.0000x reference)
#include <cuda_runtime.h>
#include <cuda_bf16.h>
#include <cstdint>

#define DINL __device__ __forceinline__

// ---------------------------------------------------------------------------
// DCNv2 forward via mma.sync bf16-split (3-pass) GEMM, pipelined. sm_80 PTX.
// B=4, Cin=Cout=256, H=W=64, 3x3, s=1, p=1, d=1, g=dg=1.
// ---------------------------------------------------------------------------

constexpr int CIN = 256, COUT = 256, HH = 64, WW = 64, HWp = 4096, KTAPS = 9;
constexpr int NPX = 128, NCHUNK = 36, NTHR = 512;

// Pre-swizzled bf16 weights: [chunk][hi plane 32KB | lo plane 32KB]
__device__ __align__(16) __nv_bfloat16 g_W[(size_t)NCHUNK * 2 * 256 * 64];

// SMEM layout (bytes)
constexpr int SM_A   = 0;        // 2 bufs x 65536 (hi 32K @ +0, lo @ +32768)
constexpr int SM_B   = 131072;   // 2 bufs x 32768 (hi 16K @ +0, lo @ +16384)
constexpr int SM_T   = 196608;   // 2 bufs x 4096  (w 2048 @ +0, idx @ +2048)
constexpr int SM_TOTAL = 204800;

// ------------------------------- PTX helpers -------------------------------
DINL uint32_t smem_u32(const void* p) {
    uint32_t a;
    asm("{ .reg .u64 t; cvta.to.shared.u64 t, %1; cvt.u32.u64 %0, t; }"
        : "=r"(a) : "l"(p));
    return a;
}
DINL void ldsm4(uint32_t& r0, uint32_t& r1, uint32_t& r2, uint32_t& r3, uint32_t a) {
    asm volatile("ldmatrix.sync.aligned.m8n8.x4.shared.b16 {%0,%1,%2,%3}, [%4];"
                 : "=r"(r0), "=r"(r1), "=r"(r2), "=r"(r3) : "r"(a));
}
DINL void mma_bf16(float* d, const uint32_t* a, const uint32_t* b) {
    asm volatile(
        "mma.sync.aligned.m16n8k16.row.col.f32.bf16.bf16.f32 "
        "{%0,%1,%2,%3},{%4,%5,%6,%7},{%8,%9},{%0,%1,%2,%3};"
        : "+f"(d[0]), "+f"(d[1]), "+f"(d[2]), "+f"(d[3])
        : "r"(a[0]), "r"(a[1]), "r"(a[2]), "r"(a[3]), "r"(b[0]), "r"(b[1]));
}
DINL uint32_t bf2(float hi, float lo) {   // low 16 bits <- lo
    uint32_t r;
    asm("cvt.rn.bf16x2.f32 %0, %1, %2;" : "=r"(r) : "f"(hi), "f"(lo));
    return r;
}
DINL void cp16(uint32_t dst, const void* src) {
    asm volatile("cp.async.cg.shared.global [%0], [%1], 16;"
                 :: "r"(dst), "l"(src) : "memory");
}
DINL void cp_commit() { asm volatile("cp.async.commit_group;" ::: "memory"); }
DINL void cp_wait0()  { asm volatile("cp.async.wait_group 0;" ::: "memory"); }

// --------------------------- weight prep kernel -----------------------------
__global__ void prep_weights(const float* __restrict__ w)
{
    int i = blockIdx.x * blockDim.x + threadIdx.x;   // 36*256*64
    if (i >= NCHUNK * 256 * 64) return;
    int j  = i & 63;            // cin within chunk
    int o  = (i >> 6) & 255;    // cout row
    int ch = i >> 14;           // chunk
    int tap = ch >> 2, cb = ch & 3;
    int c = cb * 64 + j;
    float v = w[((size_t)o * CIN + c) * KTAPS + tap];
    __nv_bfloat16 hi = __float2bfloat16(v);
    __nv_bfloat16 lo = __float2bfloat16(v - __bfloat162float(hi));
    uint32_t swb = ((uint32_t)(j * 2)) ^ (((uint32_t)o & 7u) << 4);
    size_t base = (size_t)ch * 32768 + (size_t)o * 64 + (swb >> 1);
    g_W[base]         = hi;
    g_W[base + 16384] = lo;
}

// -------------------------------- main kernel -------------------------------
__global__ __launch_bounds__(NTHR, 1)
void mdcn_hmma(const float* __restrict__ x, const float* __restrict__ offp,
               const float* __restrict__ maskp, const float* __restrict__ bias,
               float* __restrict__ out)
{
    extern __shared__ char smem[];
    const uint32_t sb = smem_u32(smem);
    const int tid  = threadIdx.x;
    const int wid  = tid >> 5, lane = tid & 31;

    const int b  = blockIdx.x >> 5;
    const int p0 = (blockIdx.x & 31) * NPX;
    const float* xb = x     + (size_t)b * CIN * HWp;
    const float* ob = offp  + (size_t)b * 2 * KTAPS * HWp;
    const float* mb = maskp + (size_t)b * KTAPS * HWp;

    // mma role: 16 warps = 4m x 4n, warp tile 64x32
    const int m_w = (wid & 3) * 64;
    const int n_w = (wid >> 2) * 32;
    const int a_rowpart = (lane & 7) + ((lane >> 3) & 1) * 8;
    const int a_colsel  = ((lane >> 4) & 1) * 16;
    const uint32_t a_swx = (uint32_t)(lane & 7) << 4;
    const int b_row = lane >> 2;
    const uint32_t b_swx = (uint32_t)(b_row & 7) << 4;
    const uint32_t b_kc  = (uint32_t)(lane & 3) * 4;

    // gather role: px + 16-cin slice
    const int px  = tid & 127;
    const int cg  = (tid >> 7) * 16;           // 0,16,32,48
    const uint32_t psw = ((uint32_t)px & 7u) << 4;

    float acc[4][4][4];
    #pragma unroll
    for (int i = 0; i < 4; i++)
        #pragma unroll
        for (int j = 0; j < 4; j++)
            #pragma unroll
            for (int q = 0; q < 4; q++) acc[i][j][q] = 0.f;

    // ---- table compute macro-block ----------------------------------------
    #define MAKE_TABLES(TAP, TB)                                               \
    do { if (tid < 128) {                                                      \
        float* tw = (float*)(smem + SM_T + (TB) * 4096);                       \
        int*   ti = (int*)(smem + SM_T + (TB) * 4096 + 2048);                  \
        const int p  = p0 + tid;                                               \
        const int ho = p >> 6, wo = p & 63;                                    \
        const int kh = (TAP) / 3, kw = (TAP) - kh * 3;                         \
        const float dy = ob[(2 * (TAP))     * HWp + p];                        \
        const float dx = ob[(2 * (TAP) + 1) * HWp + p];                        \
        const float m  = mb[(TAP) * HWp + p];                                  \
        const float sy = (float)(ho - 1 + kh) + dy;                            \
        const float sx = (float)(wo - 1 + kw) + dx;                            \
        const float y0f = floorf(sy), x0f = floorf(sx);                        \
        const float wy = sy - y0f, wx = sx - x0f;                              \
        const int y0 = (int)y0f, x0 = (int)x0f;                                \
        const int y1 = y0 + 1, x1 = x0 + 1;                                    \
        const float vy0 = (y0 >= 0 && y0 < HH) ? 1.f : 0.f;                    \
        const float vy1 = (y1 >= 0 && y1 < HH) ? 1.f : 0.f;                    \
        const float vx0 = (x0 >= 0 && x0 < WW) ? 1.f : 0.f;                    \
        const float vx1 = (x1 >= 0 && x1 < WW) ? 1.f : 0.f;                    \
        const int cy0 = min(max(y0, 0), HH - 1);                               \
        const int cy1 = min(max(y1, 0), HH - 1);                               \
        const int cx0 = min(max(x0, 0), WW - 1);                               \
        const int cx1 = min(max(x1, 0), WW - 1);                               \
        ti[tid]       = cy0 * WW + cx0;                                        \
        ti[128 + tid] = cy0 * WW + cx1;                                        \
        ti[256 + tid] = cy1 * WW + cx0;                                        \
        ti[384 + tid] = cy1 * WW + cx1;                                        \
        tw[tid]       = (1.f - wy) * (1.f - wx) * m * vy0 * vx0;               \
        tw[128 + tid] = (1.f - wy) * wx         * m * vy0 * vx1;               \
        tw[256 + tid] = wy * (1.f - wx)         * m * vy1 * vx0;               \
        tw[384 + tid] = wy * wx                 * m * vy1 * vx1;               \
    } } while (0)

    // ---- A tile cp.async macro --------------------------------------------
    #define ISSUE_A(CC, BUF)                                                   \
    do {                                                                       \
        const char* asrc = (const char*)g_W + (size_t)(CC) * 65536;            \
        const uint32_t adst = sb + SM_A + (BUF) * 65536;                       \
        _Pragma("unroll")                                                      \
        for (int t = 0; t < 8; t++)                                            \
            cp16(adst + (tid + t * 512) * 16, asrc + (size_t)(tid + t * 512) * 16); \
        cp_commit();                                                           \
    } while (0)

    // ---- B gather macro ----------------------------------------------------
    #define GATHER_B(CC, BUF)                                                  \
    do {                                                                       \
        const int tb = ((CC) >> 2) & 1;                                        \
        const float* tw = (const float*)(smem + SM_T + tb * 4096);             \
        const int*   ti = (const int*)(smem + SM_T + tb * 4096 + 2048);        \
        const float w0 = tw[px],       w1 = tw[128 + px];                      \
        const float w2 = tw[256 + px], w3 = tw[384 + px];                      \
        const int   i0 = ti[px],       i1 = ti[128 + px];                      \
        const int   i2 = ti[256 + px], i3 = ti[384 + px];                      \
        const float* xc = xb + (size_t)((((CC) & 3) * 64) + cg) * HWp;         \
        uint32_t hw[8], lw[8];                                                 \
        _Pragma("unroll")                                                      \
        for (int j = 0; j < 8; j++) {                                          \
            const float* pA = xc + (size_t)(2 * j) * HWp;                      \
            const float* pB = pA + HWp;                                        \
            float a0 = w0 * __ldg(pA + i0) + w1 * __ldg(pA + i1)               \
                     + w2 * __ldg(pA + i2) + w3 * __ldg(pA + i3);              \
            float a1 = w0 * __ldg(pB + i0) + w1 * __ldg(pB + i1)               \
                     + w2 * __ldg(pB + i2) + w3 * __ldg(pB + i3);              \
            float h0 = __bfloat162float(__float2bfloat16(a0));                 \
            float h1 = __bfloat162float(__float2bfloat16(a1));                 \
            hw[j] = bf2(a1, a0);                                               \
            lw[j] = bf2(a1 - h1, a0 - h0);                                     \
        }                                                                      \
        char* rowH = smem + SM_B + (BUF) * 32768 + px * 128;                   \
        char* rowL = rowH + 16384;                                             \
        const uint32_t c0 = ((uint32_t)(cg * 2))      ^ psw;                   \
        const uint32_t c1 = ((uint32_t)(cg * 2 + 16)) ^ psw;                   \
        *(uint4*)(rowH + c0) = make_uint4(hw[0], hw[1], hw[2], hw[3]);         \
        *(uint4*)(rowH + c1) = make_uint4(hw[4], hw[5], hw[6], hw[7]);         \
        *(uint4*)(rowL + c0) = make_uint4(lw[0], lw[1], lw[2], lw[3]);         \
        *(uint4*)(rowL + c1) = make_uint4(lw[4], lw[5], lw[6], lw[7]);         \
    } while (0)

    // ---- prologue ----------------------------------------------------------
    MAKE_TABLES(0, 0);
    __syncthreads();
    ISSUE_A(0, 0);
    GATHER_B(0, 0);

    // ---- main pipelined loop ----------------------------------------------
    for (int i = 0; i < NCHUNK; i++) {
        const int cur = i & 1, nxt = cur ^ 1;
        cp_wait0();
        __syncthreads();

        if (((i + 2) & 3) == 0 && ((i + 2) >> 2) <= 8)
            MAKE_TABLES((i + 2) >> 2, ((i + 2) >> 2) & 1);

        if (i + 1 < NCHUNK) {
            ISSUE_A(i + 1, nxt);
            GATHER_B(i + 1, nxt);
        }

        // ---- MMA on buffers (cur): 4 k16 steps x 3 split passes ------------
        const uint32_t sAhi = sb + SM_A + cur * 65536;
        const uint32_t sAlo = sAhi + 32768;
        const int      bH   = SM_B + cur * 32768;
        const int      bL   = bH + 16384;
        const uint32_t aRow = (uint32_t)(m_w + a_rowpart) * 128u;
        const uint32_t bBase = (uint32_t)(n_w + b_row) * 128u;

        #pragma unroll
        for (int ks = 0; ks < 4; ks++) {
            const uint32_t kb = (uint32_t)ks * 32u;
            const uint32_t aCol = (kb + (uint32_t)a_colsel) ^ a_swx;
            uint32_t ah[4][4], bh[4][2], bl[4][2];
            #pragma unroll
            for (int im = 0; im < 4; im++)
                ldsm4(ah[im][0], ah[im][1], ah[im][2], ah[im][3],
                      sAhi + aRow + (uint32_t)im * 2048u + aCol);
            #pragma unroll
            for (int in = 0; in < 4; in++) {
                const uint32_t base = bBase + (uint32_t)in * 1024u;
                bh[in][0] = *(const uint32_t*)(smem + (bH + base + ((kb + b_kc) ^ b_swx)));
                bh[in][1] = *(const uint32_t*)(smem + (bH + base + ((kb + 16 + b_kc) ^ b_swx)));
            }
            #pragma unroll
            for (int im = 0; im < 4; im++)
                #pragma unroll
                for (int in = 0; in < 4; in++)
                    mma_bf16(acc[im][in], ah[im], bh[in]);       // hi*hi
            #pragma unroll
            for (int in = 0; in < 4; in++) {
                const uint32_t base = bBase + (uint32_t)in * 1024u;
                bl[in][0] = *(const uint32_t*)(smem + (bL + base + ((kb + b_kc) ^ b_swx)));
                bl[in][1] = *(const uint32_t*)(smem + (bL + base + ((kb + 16 + b_kc) ^ b_swx)));
            }
            #pragma unroll
            for (int im = 0; im < 4; im++)
                #pragma unroll
                for (int in = 0; in < 4; in++)
                    mma_bf16(acc[im][in], ah[im], bl[in]);       // hi*lo
            #pragma unroll
            for (int im = 0; im < 4; im++)
                ldsm4(ah[im][0], ah[im][1], ah[im][2], ah[im][3],
                      sAlo + aRow + (uint32_t)im * 2048u + aCol);
            #pragma unroll
            for (int im = 0; im < 4; im++)
                #pragma unroll
                for (int in = 0; in < 4; in++)
                    mma_bf16(acc[im][in], ah[im], bh[in]);       // lo*hi
        }
    }

    // ---- epilogue: bias + store -------------------------------------------
    #pragma unroll
    for (int im = 0; im < 4; im++) {
        const int r0 = m_w + im * 16 + (lane >> 2);
        const int r1 = r0 + 8;
        const float bv0 = __ldg(bias + r0);
        const float bv1 = __ldg(bias + r1);
        float* o0 = out + ((size_t)b * COUT + r0) * HWp + p0 + n_w + 2 * (lane & 3);
        float* o1 = out + ((size_t)b * COUT + r1) * HWp + p0 + n_w + 2 * (lane & 3);
        #pragma unroll
        for (int in = 0; in < 4; in++) {
            *(float2*)(o0 + in * 8) = make_float2(acc[im][in][0] + bv0,
                                                  acc[im][in][1] + bv0);
            *(float2*)(o1 + in * 8) = make_float2(acc[im][in][2] + bv1,
                                                  acc[im][in][3] + bv1);
        }
    }
}

// ------------------------------- launch -------------------------------------
extern "C" void kernel_launch(void* const* d_in, const int* in_sizes, int n_in,
                              void* d_out, int out_size)
{
    const float* x    = (const float*)d_in[0];
    const float* off  = (const float*)d_in[1];
    const float* mask = (const float*)d_in[2];
    const float* w    = (const float*)d_in[3];
    const float* bias = (const float*)d_in[4];
    float* out = (float*)d_out;

    cudaFuncSetAttribute(mdcn_hmma, cudaFuncAttributeMaxDynamicSharedMemorySize, SM_TOTAL);

    prep_weights<<<(NCHUNK * 256 * 64 + 255) / 256, 256>>>(w);

    const int B = in_sizes[0] / (CIN * HWp);      // 4
    mdcn_hmma<<<B * (HWp / NPX), NTHR, SM_TOTAL>>>(x, off, mask, bias, out);
}